// round 16
// baseline (speedup 1.0000x reference)
#include <cuda_runtime.h>
#include <cuda_fp16.h>
#include <cstdint>

#define N_NODES 32768
#define N_EDGES 524288
#define DIM     256
#define DBIG    1024
#define BATCH_B 128
#define NODES_PER 256

// ---------------- scratch ---------------------------------------------------
__device__ int   g_odeg[N_NODES];
__device__ int   g_ideg[N_NODES];
__device__ int   g_rowptr[N_NODES + 1];
__device__ int   g_cursor[N_NODES];
__device__ int   g_colidx[N_EDGES];
__device__ float g_ns[N_NODES];
__device__ float g_nd[N_NODES];
__device__ __half g_hs[N_NODES * DIM];
__device__ __half g_hbig[N_NODES * DBIG];
__device__ float g_pool[BATCH_B * DBIG];
__device__ __half g_agg[N_NODES * DIM];
#define WT_L4_OFF 196608
__device__ __half g_whT[196608 + 262144];

// ---------------- helpers ---------------------------------------------------
__device__ __forceinline__ uint32_t smem_u32(const void* p) {
    uint32_t a;
    asm("{ .reg .u64 t; cvta.to.shared.u64 t, %1; cvt.u32.u64 %0, t; }" : "=r"(a) : "l"(p));
    return a;
}
#define LDSM4(r, addr)                                                          \
    asm volatile("ldmatrix.sync.aligned.m8n8.x4.shared.b16 {%0,%1,%2,%3}, [%4];"\
        : "=r"((r)[0]), "=r"((r)[1]), "=r"((r)[2]), "=r"((r)[3]) : "r"(addr))
#define MMA16816F(d, a, b)                                                      \
    asm volatile("mma.sync.aligned.m16n8k16.row.col.f32.f16.f16.f32 "           \
        "{%0,%1,%2,%3},{%4,%5,%6,%7},{%8,%9},{%0,%1,%2,%3};"                    \
        : "+f"((d)[0]), "+f"((d)[1]), "+f"((d)[2]), "+f"((d)[3])                \
        : "r"((a)[0]), "r"((a)[1]), "r"((a)[2]), "r"((a)[3]),                   \
          "r"((b)[0]), "r"((b)[1]))
#define LEAKY(v) ((v) >= 0.f ? (v) : 0.01f * (v))
#define CP_ASYNC16(sm, gp)                                                      \
    asm volatile("cp.async.cg.shared.global [%0], [%1], 16;" :: "r"(sm), "l"(gp))
#define CP_COMMIT() asm volatile("cp.async.commit_group;" ::: "memory")
#define CP_WAIT(n)  asm volatile("cp.async.wait_group %0;" :: "n"(n) : "memory")

// ---------------- graph setup ------------------------------------------------
__global__ void k_zero() {
    int i = blockIdx.x * blockDim.x + threadIdx.x;
    if (i < N_NODES) { g_odeg[i] = 0; g_ideg[i] = 0; }
}
__global__ void k_count(const int* __restrict__ src, const int* __restrict__ dst) {
    int e = blockIdx.x * blockDim.x + threadIdx.x;
    if (e < N_EDGES) { atomicAdd(&g_odeg[src[e]], 1); atomicAdd(&g_ideg[dst[e]], 1); }
}
__global__ void k_scan() {
    __shared__ int part[1024];
    int tid = threadIdx.x;
    int loc[32];
    int s = 0;
#pragma unroll
    for (int i = 0; i < 32; ++i) { loc[i] = g_ideg[tid * 32 + i]; s += loc[i]; }
    part[tid] = s;
    __syncthreads();
    for (int off = 1; off < 1024; off <<= 1) {
        int v = (tid >= off) ? part[tid - off] : 0;
        __syncthreads();
        part[tid] += v;
        __syncthreads();
    }
    int excl = part[tid] - s;
#pragma unroll
    for (int i = 0; i < 32; ++i) {
        g_rowptr[tid * 32 + i] = excl;
        g_cursor[tid * 32 + i] = excl;
        excl += loc[i];
    }
    if (tid == 1023) g_rowptr[N_NODES] = part[1023];
}
__global__ void k_scatter(const int* __restrict__ src, const int* __restrict__ dst) {
    int e = blockIdx.x * blockDim.x + threadIdx.x;
    if (e < N_EDGES) { int p = atomicAdd(&g_cursor[dst[e]], 1); g_colidx[p] = src[e]; }
}
__global__ void k_norms() {
    int i = blockIdx.x * blockDim.x + threadIdx.x;
    if (i < N_NODES) {
        int od = g_odeg[i], id = g_ideg[i];
        g_ns[i] = (od > 0) ? rsqrtf((float)od) : 1.0f;
        g_nd[i] = (id > 0) ? rsqrtf((float)id) : 1.0f;
    }
}
__global__ void k_scale_x(const float* __restrict__ x, __half* __restrict__ hs) {
    int i = blockIdx.x * blockDim.x + threadIdx.x;
    if (i < N_NODES * (DIM / 4)) {
        int row = i >> 6;
        float s = g_ns[row];
        float4 v = *(const float4*)&x[i * 4];
        __half2 h0 = __floats2half2_rn(v.x * s, v.y * s);
        __half2 h1 = __floats2half2_rn(v.z * s, v.w * s);
        uint2 p = make_uint2(*(uint32_t*)&h0, *(uint32_t*)&h1);
        *(uint2*)&hs[i * 4] = p;
    }
}

// ---------------- weight transpose -> single fp16 ----------------------------
__global__ void k_prep_w(const float* __restrict__ W, int N,
                         __half* __restrict__ oh) {
    __shared__ float t[32][33];
    int n = blockIdx.x * 32 + threadIdx.x;
    int kb = blockIdx.y * 32;
#pragma unroll
    for (int i = 0; i < 4; ++i) {
        int k = kb + threadIdx.y + i * 8;
        t[threadIdx.y + i * 8][threadIdx.x] = W[k * N + n];
    }
    __syncthreads();
    int k2 = kb + threadIdx.x;
#pragma unroll
    for (int i = 0; i < 4; ++i) {
        int n2 = blockIdx.x * 32 + threadIdx.y + i * 8;
        oh[n2 * 256 + k2] = __float2half_rn(t[threadIdx.x][threadIdx.y + i * 8]);
    }
}

// ---------------- aggregation (fp16 reads, fp32 accum) -> single fp16 --------
__device__ __forceinline__ void acc8(float* acc, uint4 v) {
    const __half2* h = (const __half2*)&v;
#pragma unroll
    for (int i = 0; i < 4; ++i) {
        float2 f = __half22float2(h[i]);
        acc[i * 2 + 0] += f.x;
        acc[i * 2 + 1] += f.y;
    }
}
__global__ void __launch_bounds__(256) k_aggregate(const __half* __restrict__ hs,
                                                   __half* __restrict__ agg) {
    int node = blockIdx.x * 8 + (threadIdx.x >> 5);
    int c = (threadIdx.x & 31) * 8;
    int beg = g_rowptr[node], end = g_rowptr[node + 1];
    float acc[8];
#pragma unroll
    for (int i = 0; i < 8; ++i) acc[i] = 0.f;
    int e = beg;
    for (; e + 4 <= end; e += 4) {
        int s0 = g_colidx[e + 0], s1 = g_colidx[e + 1];
        int s2 = g_colidx[e + 2], s3 = g_colidx[e + 3];
        uint4 v0 = *(const uint4*)&hs[s0 * DIM + c];
        uint4 v1 = *(const uint4*)&hs[s1 * DIM + c];
        uint4 v2 = *(const uint4*)&hs[s2 * DIM + c];
        uint4 v3 = *(const uint4*)&hs[s3 * DIM + c];
        acc8(acc, v0); acc8(acc, v1); acc8(acc, v2); acc8(acc, v3);
    }
    for (; e < end; ++e) {
        int s0 = g_colidx[e];
        uint4 v0 = *(const uint4*)&hs[s0 * DIM + c];
        acc8(acc, v0);
    }
    float nd = g_nd[node];
    uint32_t w[4];
#pragma unroll
    for (int i = 0; i < 4; ++i) {
        __half2 hh = __floats2half2_rn(acc[i * 2 + 0] * nd, acc[i * 2 + 1] * nd);
        w[i] = *(uint32_t*)&hh;
    }
    *(uint4*)&agg[node * DIM + c] = *(uint4*)w;
}

#define APAD 40
#define ABUF_B (128 * APAD * 2)   // layer-4 kernel buffers (10240)
#define BBUF_B (256 * APAD * 2)   // 20480

// ---------------- fused GEMM(64x256,K=256)+leaky+LN+ns, occ 2 ----------------
// 256 threads, 8 warps all along N (warp tile 64x32).  grid.x = M/64 = 512.
// dynamic smem layout (bytes):
//   [0,10240)       sA  2 bufs (64*40*2 each = 5120)
//   [10240,51200)   sB  2 bufs (256*40*2 each = 20480)
//   [51200,52224)   bias (256 f)
//   [52224,54272)   sS  (64x8 f)
//   [54272,56320)   sQ
//   [56320,56576)   sMean (64 f)
//   [56576,56832)   sSc
#define GA_BUF 5120
#define GB_BUF 20480
#define GLN_SMEM 56832

__global__ void __launch_bounds__(256, 2) k_gemm_ln(
    const __half* __restrict__ A, const __half* __restrict__ B,
    const float* __restrict__ bias, __half* __restrict__ out)
{
    extern __shared__ __align__(16) char dsm[];
    float* sBias = (float*)(dsm + 51200);
    float (*sS)[8] = (float(*)[8])(dsm + 52224);
    float (*sQ)[8] = (float(*)[8])(dsm + 54272);
    float* sMean = (float*)(dsm + 56320);
    float* sSc   = (float*)(dsm + 56576);

    int tid = threadIdx.x;
    int wid = tid >> 5, lane = tid & 31;
    int m0 = blockIdx.x * 64;
    int wn = wid * 32;

    if (tid < 256) sBias[tid] = bias[tid];

    float c[4][4][4];
#pragma unroll
    for (int i = 0; i < 4; ++i)
#pragma unroll
        for (int j = 0; j < 4; ++j) {
            c[i][j][0] = 0.f; c[i][j][1] = 0.f; c[i][j][2] = 0.f; c[i][j][3] = 0.f;
        }

    uint32_t uA = smem_u32(dsm);
    uint32_t uB = uA + 2 * GA_BUF;
    int aRow = (lane & 15) * APAD + (lane >> 4) * 8;
    int bRow = (wn + ((lane >> 4) & 1) * 8 + (lane & 7)) * APAD + ((lane >> 3) & 1) * 8;

    // copy indices: A 64 rows x 4 segs = 256 slots (1 iter); B 1024 slots (4 iters)
    int caRow = tid >> 2, caSeg = tid & 3;

    {
        CP_ASYNC16(uA + (caRow * APAD + caSeg * 8) * 2,
                   &A[(long)(m0 + caRow) * 256 + caSeg * 8]);
#pragma unroll
        for (int it = 0; it < 4; ++it) {
            int s = tid + it * 256;
            int row = s >> 2, seg = s & 3;
            CP_ASYNC16(uB + (row * APAD + seg * 8) * 2,
                       &B[(long)row * 256 + seg * 8]);
        }
        CP_COMMIT();
    }

    for (int ch = 0; ch < 8; ++ch) {
        if (ch < 7) {
            int k0 = (ch + 1) * 32;
            uint32_t ab = uA + ((ch + 1) & 1) * GA_BUF;
            uint32_t bb = uB + ((ch + 1) & 1) * GB_BUF;
            CP_ASYNC16(ab + (caRow * APAD + caSeg * 8) * 2,
                       &A[(long)(m0 + caRow) * 256 + k0 + caSeg * 8]);
#pragma unroll
            for (int it = 0; it < 4; ++it) {
                int s = tid + it * 256;
                int row = s >> 2, seg = s & 3;
                CP_ASYNC16(bb + (row * APAD + seg * 8) * 2,
                           &B[(long)row * 256 + k0 + seg * 8]);
            }
            CP_COMMIT();
            CP_WAIT(1);
        } else {
            CP_WAIT(0);
        }
        __syncthreads();
        uint32_t ua = uA + (ch & 1) * GA_BUF;
        uint32_t ub = uB + (ch & 1) * GB_BUF;
#pragma unroll
        for (int kk = 0; kk < 2; ++kk) {
            int kb = kk * 16;
            uint32_t b[4][2];
#pragma unroll
            for (int nj2 = 0; nj2 < 2; ++nj2) {
                uint32_t off = (uint32_t)(bRow + nj2 * 16 * APAD + kb) * 2;
                uint32_t r[4];
                LDSM4(r, ub + off);
                b[nj2 * 2 + 0][0] = r[0]; b[nj2 * 2 + 0][1] = r[1];
                b[nj2 * 2 + 1][0] = r[2]; b[nj2 * 2 + 1][1] = r[3];
            }
#pragma unroll
            for (int mi = 0; mi < 4; ++mi) {
                uint32_t off = (uint32_t)(aRow + mi * 16 * APAD + kb) * 2;
                uint32_t a[4];
                LDSM4(a, ua + off);
#pragma unroll
                for (int n8 = 0; n8 < 4; ++n8) {
                    MMA16816F(c[mi][n8], a, b[n8]);
                }
            }
        }
        __syncthreads();
    }

    // ---- per-row LN stats (rows 0..63 of this tile; one slot per warp) ----
    int lr = lane >> 2, lc = (lane & 3) * 2;
#pragma unroll
    for (int mi = 0; mi < 4; ++mi) {
        float s0 = 0.f, q0 = 0.f, s1 = 0.f, q1 = 0.f;
#pragma unroll
        for (int n8 = 0; n8 < 4; ++n8) {
            int col = wn + n8 * 8 + lc;
            float b0 = sBias[col], b1 = sBias[col + 1];
            float v0 = LEAKY(c[mi][n8][0] + b0);
            float v1 = LEAKY(c[mi][n8][1] + b1);
            float v2 = LEAKY(c[mi][n8][2] + b0);
            float v3 = LEAKY(c[mi][n8][3] + b1);
            s0 += v0 + v1; q0 += v0 * v0 + v1 * v1;
            s1 += v2 + v3; q1 += v2 * v2 + v3 * v3;
        }
#pragma unroll
        for (int off = 1; off < 4; off <<= 1) {
            s0 += __shfl_xor_sync(0xffffffffu, s0, off);
            q0 += __shfl_xor_sync(0xffffffffu, q0, off);
            s1 += __shfl_xor_sync(0xffffffffu, s1, off);
            q1 += __shfl_xor_sync(0xffffffffu, q1, off);
        }
        if ((lane & 3) == 0) {
            int r0 = mi * 16 + lr;
            sS[r0][wid] = s0; sQ[r0][wid] = q0;
            sS[r0 + 8][wid] = s1; sQ[r0 + 8][wid] = q1;
        }
    }
    __syncthreads();
    if (tid < 64) {
        float S = 0.f, Q = 0.f;
#pragma unroll
        for (int w = 0; w < 8; ++w) { S += sS[tid][w]; Q += sQ[tid][w]; }
        float mean = S * (1.0f / 256.0f);
        float var = Q * (1.0f / 256.0f) - mean * mean;
        sMean[tid] = mean;
        sSc[tid] = g_ns[m0 + tid] * rsqrtf(var + 1e-5f);
    }
    __syncthreads();

    // ---- normalize + store fp16 ----
#pragma unroll
    for (int mi = 0; mi < 4; ++mi) {
        int r0 = mi * 16 + lr;
        float mu0 = sMean[r0], sc0 = sSc[r0];
        float mu1 = sMean[r0 + 8], sc1 = sSc[r0 + 8];
#pragma unroll
        for (int n8 = 0; n8 < 4; ++n8) {
            int col = wn + n8 * 8 + lc;
            float b0 = sBias[col], b1 = sBias[col + 1];
            float v0 = LEAKY(c[mi][n8][0] + b0);
            float v1 = LEAKY(c[mi][n8][1] + b1);
            float v2 = LEAKY(c[mi][n8][2] + b0);
            float v3 = LEAKY(c[mi][n8][3] + b1);
            __half2 h0 = __floats2half2_rn((v0 - mu0) * sc0, (v1 - mu0) * sc0);
            __half2 h1 = __floats2half2_rn((v2 - mu1) * sc1, (v3 - mu1) * sc1);
            *(__half2*)&out[(long)(m0 + r0) * 256 + col] = h0;
            *(__half2*)&out[(long)(m0 + r0 + 8) * 256 + col] = h1;
        }
    }
}

// ---------------- fp16 GEMM (layer 4), cp.async 2-stage ----------------------
__global__ void __launch_bounds__(256, 2) k_gemm_mma(
    const __half* __restrict__ A,
    const __half* __restrict__ B,
    const float* __restrict__ bias, __half* __restrict__ out, int ldout)
{
    __shared__ __align__(16) __half sA[2][128 * APAD];
    __shared__ __align__(16) __half sB[2][128 * APAD];
    __shared__ float sBias[128];

    int tid = threadIdx.x;
    int wid = tid >> 5, lane = tid & 31;
    int m0 = blockIdx.y * 128, n0 = blockIdx.x * 128;
    int wm = (wid & 1) * 64, wn = (wid >> 1) * 32;

    if (tid < 128) sBias[tid] = bias[n0 + tid];

    float c[4][4][4];
#pragma unroll
    for (int i = 0; i < 4; ++i)
#pragma unroll
        for (int j = 0; j < 4; ++j) {
            c[i][j][0] = 0.f; c[i][j][1] = 0.f; c[i][j][2] = 0.f; c[i][j][3] = 0.f;
        }

    uint32_t uA0 = smem_u32(sA), uB0 = smem_u32(sB);
    int aRow = (wm + (lane & 15)) * APAD + (lane >> 4) * 8;
    int bRow = (wn + ((lane >> 4) & 1) * 8 + (lane & 7)) * APAD + ((lane >> 3) & 1) * 8;

    {
#pragma unroll
        for (int it = 0; it < 2; ++it) {
            int s = tid + it * 256;
            int row = s >> 2, seg = s & 3;
            CP_ASYNC16(uA0 + (row * APAD + seg * 8) * 2,
                       &A[(long)(m0 + row) * 256 + seg * 8]);
            CP_ASYNC16(uB0 + (row * APAD + seg * 8) * 2,
                       &B[(long)(n0 + row) * 256 + seg * 8]);
        }
        CP_COMMIT();
    }

    for (int ch = 0; ch < 8; ++ch) {
        if (ch < 7) {
            int k0 = (ch + 1) * 32;
            uint32_t ab = uA0 + ((ch + 1) & 1) * ABUF_B;
            uint32_t bb = uB0 + ((ch + 1) & 1) * ABUF_B;
#pragma unroll
            for (int it = 0; it < 2; ++it) {
                int s = tid + it * 256;
                int row = s >> 2, seg = s & 3;
                CP_ASYNC16(ab + (row * APAD + seg * 8) * 2,
                           &A[(long)(m0 + row) * 256 + k0 + seg * 8]);
                CP_ASYNC16(bb + (row * APAD + seg * 8) * 2,
                           &B[(long)(n0 + row) * 256 + k0 + seg * 8]);
            }
            CP_COMMIT();
            CP_WAIT(1);
        } else {
            CP_WAIT(0);
        }
        __syncthreads();
        uint32_t ua = uA0 + (ch & 1) * ABUF_B;
        uint32_t ub = uB0 + (ch & 1) * ABUF_B;
#pragma unroll
        for (int kk = 0; kk < 2; ++kk) {
            int kb = kk * 16;
            uint32_t b[4][2];
#pragma unroll
            for (int nj2 = 0; nj2 < 2; ++nj2) {
                uint32_t off = (uint32_t)(bRow + nj2 * 16 * APAD + kb) * 2;
                uint32_t r[4];
                LDSM4(r, ub + off);
                b[nj2 * 2 + 0][0] = r[0]; b[nj2 * 2 + 0][1] = r[1];
                b[nj2 * 2 + 1][0] = r[2]; b[nj2 * 2 + 1][1] = r[3];
            }
#pragma unroll
            for (int mi = 0; mi < 4; ++mi) {
                uint32_t off = (uint32_t)(aRow + mi * 16 * APAD + kb) * 2;
                uint32_t a[4];
                LDSM4(a, ua + off);
#pragma unroll
                for (int n8 = 0; n8 < 4; ++n8) {
                    MMA16816F(c[mi][n8], a, b[n8]);
                }
            }
        }
        __syncthreads();
    }

    int lr = lane >> 2, lc = (lane & 3) * 2;
#pragma unroll
    for (int mi = 0; mi < 4; ++mi) {
#pragma unroll
        for (int n8 = 0; n8 < 4; ++n8) {
            int col = wn + n8 * 8 + lc;
            int row = m0 + wm + mi * 16 + lr;
            float b0 = sBias[col], b1 = sBias[col + 1];
            *(__half2*)&out[(long)row * ldout + n0 + col] =
                __floats2half2_rn(c[mi][n8][0] + b0, c[mi][n8][1] + b1);
            *(__half2*)&out[(long)(row + 8) * ldout + n0 + col] =
                __floats2half2_rn(c[mi][n8][2] + b0, c[mi][n8][3] + b1);
        }
    }
}

// ---------------- fused leaky + LN + mean-pool + pool-LN (fp16 input) --------
__global__ void __launch_bounds__(256) k_lnpool(const __half* __restrict__ hbig,
                                                float* __restrict__ pool) {
    __shared__ float sp[DBIG];
    __shared__ float ss[8], qq[8];
    __shared__ float s_mean, s_rstd;
    int b = blockIdx.x;
    int tid = threadIdx.x;
    int wid = tid >> 5, lane = tid & 31;

#pragma unroll
    for (int j = 0; j < 4; ++j) sp[tid * 4 + j] = 0.f;
    __syncthreads();

    float acc[32];
#pragma unroll
    for (int i = 0; i < 32; ++i) acc[i] = 0.f;

    for (int r = wid; r < NODES_PER; r += 8) {
        const __half* row = hbig + ((long)b * NODES_PER + r) * DBIG;
        float f[32];
        float s = 0.f, q = 0.f;
#pragma unroll
        for (int t = 0; t < 4; ++t) {
            uint4 v = *(const uint4*)&row[lane * 8 + t * 256];
            const __half2* h2 = (const __half2*)&v;
#pragma unroll
            for (int i = 0; i < 4; ++i) {
                float2 f2 = __half22float2(h2[i]);
                f2.x = LEAKY(f2.x);
                f2.y = LEAKY(f2.y);
                f[t * 8 + i * 2 + 0] = f2.x;
                f[t * 8 + i * 2 + 1] = f2.y;
                s += f2.x + f2.y;
                q += f2.x * f2.x + f2.y * f2.y;
            }
        }
#pragma unroll
        for (int off = 1; off < 32; off <<= 1) {
            s += __shfl_xor_sync(0xffffffffu, s, off);
            q += __shfl_xor_sync(0xffffffffu, q, off);
        }
        float mean = s * (1.0f / 1024.0f);
        float var = q * (1.0f / 1024.0f) - mean * mean;
        float rstd = rsqrtf(var + 1e-5f);
#pragma unroll
        for (int i = 0; i < 32; ++i) acc[i] += (f[i] - mean) * rstd;
    }
#pragma unroll
    for (int t = 0; t < 4; ++t)
#pragma unroll
        for (int j = 0; j < 8; ++j)
            atomicAdd(&sp[lane * 8 + t * 256 + j], acc[t * 8 + j]);
    __syncthreads();

    const float inv = 1.0f / (float)NODES_PER;
    float v0 = sp[tid * 4 + 0] * inv, v1 = sp[tid * 4 + 1] * inv;
    float v2 = sp[tid * 4 + 2] * inv, v3 = sp[tid * 4 + 3] * inv;
    float s = (v0 + v1) + (v2 + v3);
    float q = (v0 * v0 + v1 * v1) + (v2 * v2 + v3 * v3);
#pragma unroll
    for (int off = 1; off < 32; off <<= 1) {
        s += __shfl_xor_sync(0xffffffffu, s, off);
        q += __shfl_xor_sync(0xffffffffu, q, off);
    }
    if (lane == 0) { ss[wid] = s; qq[wid] = q; }
    __syncthreads();
    if (tid == 0) {
        float S = 0.f, Q = 0.f;
#pragma unroll
        for (int w = 0; w < 8; ++w) { S += ss[w]; Q += qq[w]; }
        float mean = S * (1.0f / 1024.0f);
        float var = Q * (1.0f / 1024.0f) - mean * mean;
        s_mean = mean;
        s_rstd = rsqrtf(var + 1e-5f);
    }
    __syncthreads();
    float mean = s_mean, rstd = s_rstd;
    float4 o;
    o.x = (v0 - mean) * rstd; o.y = (v1 - mean) * rstd;
    o.z = (v2 - mean) * rstd; o.w = (v3 - mean) * rstd;
    *(float4*)&pool[b * DBIG + tid * 4] = o;
}

// ---------------- heads ------------------------------------------------------
__global__ void k_out_init(const float* __restrict__ bm, const float* __restrict__ bs,
                           float* __restrict__ out) {
    int i = blockIdx.x * blockDim.x + threadIdx.x;
    if (i < 2 * BATCH_B * DBIG) {
        int n = i & (DBIG - 1);
        out[i] = (i < BATCH_B * DBIG) ? bm[n] : bs[n];
    }
}
__global__ void __launch_bounds__(256) k_head(const float* __restrict__ pool,
                                              const float* __restrict__ Wm,
                                              const float* __restrict__ Ws,
                                              float* __restrict__ out) {
    const float* W = blockIdx.z ? Ws : Wm;
    float* o = out + blockIdx.z * (BATCH_B * DBIG);
    int n0 = blockIdx.x * 64;
    int kc0 = blockIdx.y * 128;
    int tid = threadIdx.x;
    int col = tid & 63;
    int ty = tid >> 6;
    __shared__ float Ap[32 * 136];
    __shared__ float Wsm[32 * 64];
    float acc[32];
#pragma unroll
    for (int r = 0; r < 32; ++r) acc[r] = 0.f;

    for (int kk = 0; kk < 128; kk += 32) {
#pragma unroll
        for (int t = 0; t < 4; ++t) {
            int s = tid + t * 256;
            int row = s >> 3, kq = s & 7;
            float4 v = *(const float4*)&pool[row * DBIG + kc0 + kk + kq * 4];
            Ap[(kq * 4 + 0) * 136 + row] = v.x;
            Ap[(kq * 4 + 1) * 136 + row] = v.y;
            Ap[(kq * 4 + 2) * 136 + row] = v.z;
            Ap[(kq * 4 + 3) * 136 + row] = v.w;
        }
#pragma unroll
        for (int t = 0; t < 2; ++t) {
            int s = tid + t * 256;
            int kr = s >> 4, c4 = s & 15;
            *(float4*)&Wsm[kr * 64 + c4 * 4] =
                *(const float4*)&W[(kc0 + kk + kr) * DBIG + n0 + c4 * 4];
        }
        __syncthreads();
#pragma unroll
        for (int k = 0; k < 32; ++k) {
            float b = Wsm[k * 64 + col];
#pragma unroll
            for (int r4 = 0; r4 < 8; ++r4) {
                float4 a = *(const float4*)&Ap[k * 136 + ty * 32 + r4 * 4];
                acc[r4 * 4 + 0] += a.x * b;
                acc[r4 * 4 + 1] += a.y * b;
                acc[r4 * 4 + 2] += a.z * b;
                acc[r4 * 4 + 3] += a.w * b;
            }
        }
        __syncthreads();
    }
#pragma unroll
    for (int r = 0; r < 32; ++r)
        atomicAdd(&o[(ty * 32 + r) * DBIG + n0 + col], acc[r]);
}

// ---------------- driver ----------------------------------------------------
extern "C" void kernel_launch(void* const* d_in, const int* in_sizes, int n_in,
                              void* d_out, int out_size) {
    const float* x   = (const float*)d_in[0];
    const int*   src = (const int*)d_in[1];
    const int*   dst = (const int*)d_in[2];
    const float* Wl[4] = { (const float*)d_in[3], (const float*)d_in[5],
                           (const float*)d_in[7], (const float*)d_in[9] };
    const float* bl[4] = { (const float*)d_in[4], (const float*)d_in[6],
                           (const float*)d_in[8], (const float*)d_in[10] };
    const float* Wm = (const float*)d_in[11];
    const float* bm = (const float*)d_in[12];
    const float* Ws = (const float*)d_in[13];
    const float* bs = (const float*)d_in[14];
    float* out = (float*)d_out;

    void *p_hs, *p_hbig, *p_pool, *p_wh, *p_ag;
    cudaGetSymbolAddress(&p_hs,   g_hs);
    cudaGetSymbolAddress(&p_hbig, g_hbig);
    cudaGetSymbolAddress(&p_pool, g_pool);
    cudaGetSymbolAddress(&p_wh,   g_whT);
    cudaGetSymbolAddress(&p_ag,   g_agg);
    __half* hs   = (__half*)p_hs;
    __half* hbig = (__half*)p_hbig;
    float* pool  = (float*)p_pool;
    __half* whT  = (__half*)p_wh;
    __half* agg  = (__half*)p_ag;

    cudaFuncSetAttribute(k_gemm_ln, cudaFuncAttributeMaxDynamicSharedMemorySize, GLN_SMEM);

    // graph preprocessing
    k_zero   <<<128, 256>>>();
    k_count  <<<2048, 256>>>(src, dst);
    k_scan   <<<1, 1024>>>();
    k_scatter<<<2048, 256>>>(src, dst);
    k_norms  <<<128, 256>>>();
    k_scale_x<<<8192, 256>>>(x, hs);

    // weight transpose (single fp16, [n][k])
    dim3 tb(32, 8);
    k_prep_w<<<dim3(8,  8), tb>>>(Wl[0], 256,  whT);
    k_prep_w<<<dim3(8,  8), tb>>>(Wl[1], 256,  whT + 65536);
    k_prep_w<<<dim3(8,  8), tb>>>(Wl[2], 256,  whT + 131072);
    k_prep_w<<<dim3(32, 8), tb>>>(Wl[3], 1024, whT + WT_L4_OFF);

    // layers 1-3: aggregate -> fused GEMM+leaky+LN+ns (M=64 tile, occ 2) -> hs
    for (int l = 0; l < 3; ++l) {
        k_aggregate<<<N_NODES / 8, 256>>>(hs, agg);
        k_gemm_ln<<<N_NODES / 64, 256, GLN_SMEM>>>(agg, whT + l * 65536, bl[l], hs);
    }
    // layer 4
    k_aggregate<<<N_NODES / 8, 256>>>(hs, agg);
    k_gemm_mma<<<dim3(8, N_NODES / 128), 256>>>(
        agg, whT + WT_L4_OFF, bl[3], hbig, 1024);

    // fused leaky+LN+pool+poolLN, then heads
    k_lnpool<<<BATCH_B, 256>>>(hbig, pool);
    k_out_init<<<512, 512>>>(bm, bs, out);
    k_head<<<dim3(16, 8, 2), 256>>>(pool, Wm, Ws, out);
}

// round 17
// speedup vs baseline: 1.0220x; 1.0220x over previous
#include <cuda_runtime.h>
#include <cuda_fp16.h>
#include <cstdint>

#define N_NODES 32768
#define N_EDGES 524288
#define DIM     256
#define DBIG    1024
#define BATCH_B 128
#define NODES_PER 256

// ---------------- scratch ---------------------------------------------------
__device__ int   g_odeg[N_NODES];
__device__ int   g_ideg[N_NODES];
__device__ int   g_rowptr[N_NODES + 1];
__device__ int   g_cursor[N_NODES];
__device__ int   g_colidx[N_EDGES];
__device__ float g_ns[N_NODES];
__device__ float g_nd[N_NODES];
__device__ __half g_hs[N_NODES * DIM];
__device__ __half g_hbig[N_NODES * DBIG];
__device__ float g_pool[BATCH_B * DBIG];
__device__ __half g_agg[N_NODES * DIM];
#define WT_L4_OFF 196608
__device__ __half g_whT[196608 + 262144];

// ---------------- helpers ---------------------------------------------------
__device__ __forceinline__ uint32_t smem_u32(const void* p) {
    uint32_t a;
    asm("{ .reg .u64 t; cvta.to.shared.u64 t, %1; cvt.u32.u64 %0, t; }" : "=r"(a) : "l"(p));
    return a;
}
#define LDSM4(r, addr)                                                          \
    asm volatile("ldmatrix.sync.aligned.m8n8.x4.shared.b16 {%0,%1,%2,%3}, [%4];"\
        : "=r"((r)[0]), "=r"((r)[1]), "=r"((r)[2]), "=r"((r)[3]) : "r"(addr))
#define MMA16816F(d, a, b)                                                      \
    asm volatile("mma.sync.aligned.m16n8k16.row.col.f32.f16.f16.f32 "           \
        "{%0,%1,%2,%3},{%4,%5,%6,%7},{%8,%9},{%0,%1,%2,%3};"                    \
        : "+f"((d)[0]), "+f"((d)[1]), "+f"((d)[2]), "+f"((d)[3])                \
        : "r"((a)[0]), "r"((a)[1]), "r"((a)[2]), "r"((a)[3]),                   \
          "r"((b)[0]), "r"((b)[1]))
#define LEAKY(v) ((v) >= 0.f ? (v) : 0.01f * (v))
#define CP_ASYNC16(sm, gp)                                                      \
    asm volatile("cp.async.cg.shared.global [%0], [%1], 16;" :: "r"(sm), "l"(gp))
#define CP_COMMIT() asm volatile("cp.async.commit_group;" ::: "memory")
#define CP_WAIT(n)  asm volatile("cp.async.wait_group %0;" :: "n"(n) : "memory")

// ---------------- graph setup ------------------------------------------------
__global__ void k_zero() {
    int i = blockIdx.x * blockDim.x + threadIdx.x;   // uint4 index; 4096 total
    if (i < N_NODES / 4) {
        *(uint4*)&g_odeg[i * 4] = make_uint4(0, 0, 0, 0);
        *(uint4*)&g_ideg[i * 4] = make_uint4(0, 0, 0, 0);
    }
}
__global__ void k_count(const int* __restrict__ src, const int* __restrict__ dst) {
    int e = blockIdx.x * blockDim.x + threadIdx.x;
    if (e < N_EDGES) { atomicAdd(&g_odeg[src[e]], 1); atomicAdd(&g_ideg[dst[e]], 1); }
}
__global__ void k_scan() {
    __shared__ int part[1024];
    int tid = threadIdx.x;
    int loc[32];
    int s = 0;
#pragma unroll
    for (int i = 0; i < 32; ++i) { loc[i] = g_ideg[tid * 32 + i]; s += loc[i]; }
    part[tid] = s;
    __syncthreads();
    for (int off = 1; off < 1024; off <<= 1) {
        int v = (tid >= off) ? part[tid - off] : 0;
        __syncthreads();
        part[tid] += v;
        __syncthreads();
    }
    int excl = part[tid] - s;
#pragma unroll
    for (int i = 0; i < 32; ++i) {
        g_rowptr[tid * 32 + i] = excl;
        g_cursor[tid * 32 + i] = excl;
        excl += loc[i];
    }
    if (tid == 1023) g_rowptr[N_NODES] = part[1023];
}
__global__ void k_scatter(const int* __restrict__ src, const int* __restrict__ dst) {
    int e = blockIdx.x * blockDim.x + threadIdx.x;
    if (e < N_EDGES) { int p = atomicAdd(&g_cursor[dst[e]], 1); g_colidx[p] = src[e]; }
}
__global__ void k_norms() {
    int i = blockIdx.x * blockDim.x + threadIdx.x;
    if (i < N_NODES) {
        int od = g_odeg[i], id = g_ideg[i];
        g_ns[i] = (od > 0) ? rsqrtf((float)od) : 1.0f;
        g_nd[i] = (id > 0) ? rsqrtf((float)id) : 1.0f;
    }
}
__global__ void k_scale_x(const float* __restrict__ x, __half* __restrict__ hs) {
    int i = blockIdx.x * blockDim.x + threadIdx.x;
    if (i < N_NODES * (DIM / 4)) {
        int row = i >> 6;
        float s = g_ns[row];
        float4 v = *(const float4*)&x[i * 4];
        __half2 h0 = __floats2half2_rn(v.x * s, v.y * s);
        __half2 h1 = __floats2half2_rn(v.z * s, v.w * s);
        uint2 p = make_uint2(*(uint32_t*)&h0, *(uint32_t*)&h1);
        *(uint2*)&hs[i * 4] = p;
    }
}

// ---------------- weight transpose -> single fp16 ----------------------------
// layers 1-3 in one launch: grid (8, 8, 3); blockIdx.z selects layer.
__global__ void k_prep_w3(const float* __restrict__ W0, const float* __restrict__ W1,
                          const float* __restrict__ W2, __half* __restrict__ oh) {
    __shared__ float t[32][33];
    const float* W = (blockIdx.z == 0) ? W0 : (blockIdx.z == 1) ? W1 : W2;
    __half* o = oh + blockIdx.z * 65536;
    int n = blockIdx.x * 32 + threadIdx.x;
    int kb = blockIdx.y * 32;
#pragma unroll
    for (int i = 0; i < 4; ++i) {
        int k = kb + threadIdx.y + i * 8;
        t[threadIdx.y + i * 8][threadIdx.x] = W[k * 256 + n];
    }
    __syncthreads();
    int k2 = kb + threadIdx.x;
#pragma unroll
    for (int i = 0; i < 4; ++i) {
        int n2 = blockIdx.x * 32 + threadIdx.y + i * 8;
        o[n2 * 256 + k2] = __float2half_rn(t[threadIdx.x][threadIdx.y + i * 8]);
    }
}
__global__ void k_prep_w(const float* __restrict__ W, int N,
                         __half* __restrict__ oh) {
    __shared__ float t[32][33];
    int n = blockIdx.x * 32 + threadIdx.x;
    int kb = blockIdx.y * 32;
#pragma unroll
    for (int i = 0; i < 4; ++i) {
        int k = kb + threadIdx.y + i * 8;
        t[threadIdx.y + i * 8][threadIdx.x] = W[k * N + n];
    }
    __syncthreads();
    int k2 = kb + threadIdx.x;
#pragma unroll
    for (int i = 0; i < 4; ++i) {
        int n2 = blockIdx.x * 32 + threadIdx.y + i * 8;
        oh[n2 * 256 + k2] = __float2half_rn(t[threadIdx.x][threadIdx.y + i * 8]);
    }
}

// ---------------- aggregation (fp16 reads, fp32 accum) -> single fp16 --------
__device__ __forceinline__ void acc8(float* acc, uint4 v) {
    const __half2* h = (const __half2*)&v;
#pragma unroll
    for (int i = 0; i < 4; ++i) {
        float2 f = __half22float2(h[i]);
        acc[i * 2 + 0] += f.x;
        acc[i * 2 + 1] += f.y;
    }
}
__global__ void __launch_bounds__(256) k_aggregate(const __half* __restrict__ hs,
                                                   __half* __restrict__ agg) {
    int node = blockIdx.x * 8 + (threadIdx.x >> 5);
    int c = (threadIdx.x & 31) * 8;
    int beg = g_rowptr[node], end = g_rowptr[node + 1];
    float acc[8];
#pragma unroll
    for (int i = 0; i < 8; ++i) acc[i] = 0.f;
    int e = beg;
    for (; e + 4 <= end; e += 4) {
        int s0 = g_colidx[e + 0], s1 = g_colidx[e + 1];
        int s2 = g_colidx[e + 2], s3 = g_colidx[e + 3];
        uint4 v0 = *(const uint4*)&hs[s0 * DIM + c];
        uint4 v1 = *(const uint4*)&hs[s1 * DIM + c];
        uint4 v2 = *(const uint4*)&hs[s2 * DIM + c];
        uint4 v3 = *(const uint4*)&hs[s3 * DIM + c];
        acc8(acc, v0); acc8(acc, v1); acc8(acc, v2); acc8(acc, v3);
    }
    for (; e < end; ++e) {
        int s0 = g_colidx[e];
        uint4 v0 = *(const uint4*)&hs[s0 * DIM + c];
        acc8(acc, v0);
    }
    float nd = g_nd[node];
    uint32_t w[4];
#pragma unroll
    for (int i = 0; i < 4; ++i) {
        __half2 hh = __floats2half2_rn(acc[i * 2 + 0] * nd, acc[i * 2 + 1] * nd);
        w[i] = *(uint32_t*)&hh;
    }
    *(uint4*)&agg[node * DIM + c] = *(uint4*)w;
}

#define APAD 40
#define ABUF_B (128 * APAD * 2)   // 10240
#define BBUF_B (256 * APAD * 2)   // 20480

// ---------------- fused GEMM(128x256,K=256)+leaky+LN+ns, cp.async 2-stage ----
#define GLN_SMEM 71680

__global__ void __launch_bounds__(512, 1) k_gemm_ln(
    const __half* __restrict__ A, const __half* __restrict__ B,
    const float* __restrict__ bias, __half* __restrict__ out)
{
    extern __shared__ __align__(16) char dsm[];
    float* sBias = (float*)(dsm + 61440);
    float (*sS)[8] = (float(*)[8])(dsm + 62464);
    float (*sQ)[8] = (float(*)[8])(dsm + 66560);
    float* sMean = (float*)(dsm + 70656);
    float* sSc   = (float*)(dsm + 71168);

    int tid = threadIdx.x;
    int wid = tid >> 5, lane = tid & 31;
    int m0 = blockIdx.x * 128;
    int wm = (wid & 1) * 64, wn = (wid >> 1) * 32;

    if (tid < 256) sBias[tid] = bias[tid];

    float c[4][4][4];
#pragma unroll
    for (int i = 0; i < 4; ++i)
#pragma unroll
        for (int j = 0; j < 4; ++j) {
            c[i][j][0] = 0.f; c[i][j][1] = 0.f; c[i][j][2] = 0.f; c[i][j][3] = 0.f;
        }

    uint32_t uA = smem_u32(dsm);
    uint32_t uB = uA + 2 * ABUF_B;
    int aRow = (wm + (lane & 15)) * APAD + (lane >> 4) * 8;
    int bRow = (wn + ((lane >> 4) & 1) * 8 + (lane & 7)) * APAD + ((lane >> 3) & 1) * 8;

    int caRow = tid >> 2, caSeg = tid & 3;

    {
        CP_ASYNC16(uA + (caRow * APAD + caSeg * 8) * 2,
                   &A[(long)(m0 + caRow) * 256 + caSeg * 8]);
#pragma unroll
        for (int it = 0; it < 2; ++it) {
            int s = tid + it * 512;
            int row = s >> 2, seg = s & 3;
            CP_ASYNC16(uB + (row * APAD + seg * 8) * 2,
                       &B[(long)row * 256 + seg * 8]);
        }
        CP_COMMIT();
    }

    for (int ch = 0; ch < 8; ++ch) {
        if (ch < 7) {
            int k0 = (ch + 1) * 32;
            uint32_t ab = uA + ((ch + 1) & 1) * ABUF_B;
            uint32_t bb = uB + ((ch + 1) & 1) * BBUF_B;
            CP_ASYNC16(ab + (caRow * APAD + caSeg * 8) * 2,
                       &A[(long)(m0 + caRow) * 256 + k0 + caSeg * 8]);
#pragma unroll
            for (int it = 0; it < 2; ++it) {
                int s = tid + it * 512;
                int row = s >> 2, seg = s & 3;
                CP_ASYNC16(bb + (row * APAD + seg * 8) * 2,
                           &B[(long)row * 256 + k0 + seg * 8]);
            }
            CP_COMMIT();
            CP_WAIT(1);
        } else {
            CP_WAIT(0);
        }
        __syncthreads();
        uint32_t ua = uA + (ch & 1) * ABUF_B;
        uint32_t ub = uB + (ch & 1) * BBUF_B;
#pragma unroll
        for (int kk = 0; kk < 2; ++kk) {
            int kb = kk * 16;
            uint32_t b[4][2];
#pragma unroll
            for (int nj2 = 0; nj2 < 2; ++nj2) {
                uint32_t off = (uint32_t)(bRow + nj2 * 16 * APAD + kb) * 2;
                uint32_t r[4];
                LDSM4(r, ub + off);
                b[nj2 * 2 + 0][0] = r[0]; b[nj2 * 2 + 0][1] = r[1];
                b[nj2 * 2 + 1][0] = r[2]; b[nj2 * 2 + 1][1] = r[3];
            }
#pragma unroll
            for (int mi = 0; mi < 4; ++mi) {
                uint32_t off = (uint32_t)(aRow + mi * 16 * APAD + kb) * 2;
                uint32_t a[4];
                LDSM4(a, ua + off);
#pragma unroll
                for (int n8 = 0; n8 < 4; ++n8) {
                    MMA16816F(c[mi][n8], a, b[n8]);
                }
            }
        }
        __syncthreads();
    }

    int lr = lane >> 2, lc = (lane & 3) * 2;
    int nslot = wid >> 1;
#pragma unroll
    for (int mi = 0; mi < 4; ++mi) {
        float s0 = 0.f, q0 = 0.f, s1 = 0.f, q1 = 0.f;
#pragma unroll
        for (int n8 = 0; n8 < 4; ++n8) {
            int col = wn + n8 * 8 + lc;
            float b0 = sBias[col], b1 = sBias[col + 1];
            float v0 = LEAKY(c[mi][n8][0] + b0);
            float v1 = LEAKY(c[mi][n8][1] + b1);
            float v2 = LEAKY(c[mi][n8][2] + b0);
            float v3 = LEAKY(c[mi][n8][3] + b1);
            s0 += v0 + v1; q0 += v0 * v0 + v1 * v1;
            s1 += v2 + v3; q1 += v2 * v2 + v3 * v3;
        }
#pragma unroll
        for (int off = 1; off < 4; off <<= 1) {
            s0 += __shfl_xor_sync(0xffffffffu, s0, off);
            q0 += __shfl_xor_sync(0xffffffffu, q0, off);
            s1 += __shfl_xor_sync(0xffffffffu, s1, off);
            q1 += __shfl_xor_sync(0xffffffffu, q1, off);
        }
        if ((lane & 3) == 0) {
            int r0 = wm + mi * 16 + lr;
            sS[r0][nslot] = s0; sQ[r0][nslot] = q0;
            sS[r0 + 8][nslot] = s1; sQ[r0 + 8][nslot] = q1;
        }
    }
    __syncthreads();
    if (tid < 128) {
        float S = 0.f, Q = 0.f;
#pragma unroll
        for (int w = 0; w < 8; ++w) { S += sS[tid][w]; Q += sQ[tid][w]; }
        float mean = S * (1.0f / 256.0f);
        float var = Q * (1.0f / 256.0f) - mean * mean;
        sMean[tid] = mean;
        sSc[tid] = g_ns[m0 + tid] * rsqrtf(var + 1e-5f);
    }
    __syncthreads();

#pragma unroll
    for (int mi = 0; mi < 4; ++mi) {
        int r0 = wm + mi * 16 + lr;
        float mu0 = sMean[r0], sc0 = sSc[r0];
        float mu1 = sMean[r0 + 8], sc1 = sSc[r0 + 8];
#pragma unroll
        for (int n8 = 0; n8 < 4; ++n8) {
            int col = wn + n8 * 8 + lc;
            float b0 = sBias[col], b1 = sBias[col + 1];
            float v0 = LEAKY(c[mi][n8][0] + b0);
            float v1 = LEAKY(c[mi][n8][1] + b1);
            float v2 = LEAKY(c[mi][n8][2] + b0);
            float v3 = LEAKY(c[mi][n8][3] + b1);
            __half2 h0 = __floats2half2_rn((v0 - mu0) * sc0, (v1 - mu0) * sc0);
            __half2 h1 = __floats2half2_rn((v2 - mu1) * sc1, (v3 - mu1) * sc1);
            *(__half2*)&out[(long)(m0 + r0) * 256 + col] = h0;
            *(__half2*)&out[(long)(m0 + r0 + 8) * 256 + col] = h1;
        }
    }
}

// ---------------- fp16 GEMM (layer 4), cp.async 2-stage ----------------------
__global__ void __launch_bounds__(256, 2) k_gemm_mma(
    const __half* __restrict__ A,
    const __half* __restrict__ B,
    const float* __restrict__ bias, __half* __restrict__ out, int ldout)
{
    __shared__ __align__(16) __half sA[2][128 * APAD];
    __shared__ __align__(16) __half sB[2][128 * APAD];
    __shared__ float sBias[128];

    int tid = threadIdx.x;
    int wid = tid >> 5, lane = tid & 31;
    int m0 = blockIdx.y * 128, n0 = blockIdx.x * 128;
    int wm = (wid & 1) * 64, wn = (wid >> 1) * 32;

    if (tid < 128) sBias[tid] = bias[n0 + tid];

    float c[4][4][4];
#pragma unroll
    for (int i = 0; i < 4; ++i)
#pragma unroll
        for (int j = 0; j < 4; ++j) {
            c[i][j][0] = 0.f; c[i][j][1] = 0.f; c[i][j][2] = 0.f; c[i][j][3] = 0.f;
        }

    uint32_t uA0 = smem_u32(sA), uB0 = smem_u32(sB);
    int aRow = (wm + (lane & 15)) * APAD + (lane >> 4) * 8;
    int bRow = (wn + ((lane >> 4) & 1) * 8 + (lane & 7)) * APAD + ((lane >> 3) & 1) * 8;

    {
#pragma unroll
        for (int it = 0; it < 2; ++it) {
            int s = tid + it * 256;
            int row = s >> 2, seg = s & 3;
            CP_ASYNC16(uA0 + (row * APAD + seg * 8) * 2,
                       &A[(long)(m0 + row) * 256 + seg * 8]);
            CP_ASYNC16(uB0 + (row * APAD + seg * 8) * 2,
                       &B[(long)(n0 + row) * 256 + seg * 8]);
        }
        CP_COMMIT();
    }

    for (int ch = 0; ch < 8; ++ch) {
        if (ch < 7) {
            int k0 = (ch + 1) * 32;
            uint32_t ab = uA0 + ((ch + 1) & 1) * ABUF_B;
            uint32_t bb = uB0 + ((ch + 1) & 1) * ABUF_B;
#pragma unroll
            for (int it = 0; it < 2; ++it) {
                int s = tid + it * 256;
                int row = s >> 2, seg = s & 3;
                CP_ASYNC16(ab + (row * APAD + seg * 8) * 2,
                           &A[(long)(m0 + row) * 256 + k0 + seg * 8]);
                CP_ASYNC16(bb + (row * APAD + seg * 8) * 2,
                           &B[(long)(n0 + row) * 256 + k0 + seg * 8]);
            }
            CP_COMMIT();
            CP_WAIT(1);
        } else {
            CP_WAIT(0);
        }
        __syncthreads();
        uint32_t ua = uA0 + (ch & 1) * ABUF_B;
        uint32_t ub = uB0 + (ch & 1) * ABUF_B;
#pragma unroll
        for (int kk = 0; kk < 2; ++kk) {
            int kb = kk * 16;
            uint32_t b[4][2];
#pragma unroll
            for (int nj2 = 0; nj2 < 2; ++nj2) {
                uint32_t off = (uint32_t)(bRow + nj2 * 16 * APAD + kb) * 2;
                uint32_t r[4];
                LDSM4(r, ub + off);
                b[nj2 * 2 + 0][0] = r[0]; b[nj2 * 2 + 0][1] = r[1];
                b[nj2 * 2 + 1][0] = r[2]; b[nj2 * 2 + 1][1] = r[3];
            }
#pragma unroll
            for (int mi = 0; mi < 4; ++mi) {
                uint32_t off = (uint32_t)(aRow + mi * 16 * APAD + kb) * 2;
                uint32_t a[4];
                LDSM4(a, ua + off);
#pragma unroll
                for (int n8 = 0; n8 < 4; ++n8) {
                    MMA16816F(c[mi][n8], a, b[n8]);
                }
            }
        }
        __syncthreads();
    }

    int lr = lane >> 2, lc = (lane & 3) * 2;
#pragma unroll
    for (int mi = 0; mi < 4; ++mi) {
#pragma unroll
        for (int n8 = 0; n8 < 4; ++n8) {
            int col = wn + n8 * 8 + lc;
            int row = m0 + wm + mi * 16 + lr;
            float b0 = sBias[col], b1 = sBias[col + 1];
            *(__half2*)&out[(long)row * ldout + n0 + col] =
                __floats2half2_rn(c[mi][n8][0] + b0, c[mi][n8][1] + b1);
            *(__half2*)&out[(long)(row + 8) * ldout + n0 + col] =
                __floats2half2_rn(c[mi][n8][2] + b0, c[mi][n8][3] + b1);
        }
    }
}

// ---------------- fused leaky + LN + mean-pool + pool-LN (fp16 input) --------
__global__ void __launch_bounds__(256) k_lnpool(const __half* __restrict__ hbig,
                                                float* __restrict__ pool) {
    __shared__ float sp[DBIG];
    __shared__ float ss[8], qq[8];
    __shared__ float s_mean, s_rstd;
    int b = blockIdx.x;
    int tid = threadIdx.x;
    int wid = tid >> 5, lane = tid & 31;

#pragma unroll
    for (int j = 0; j < 4; ++j) sp[tid * 4 + j] = 0.f;
    __syncthreads();

    float acc[32];
#pragma unroll
    for (int i = 0; i < 32; ++i) acc[i] = 0.f;

    for (int r = wid; r < NODES_PER; r += 8) {
        const __half* row = hbig + ((long)b * NODES_PER + r) * DBIG;
        float f[32];
        float s = 0.f, q = 0.f;
#pragma unroll
        for (int t = 0; t < 4; ++t) {
            uint4 v = *(const uint4*)&row[lane * 8 + t * 256];
            const __half2* h2 = (const __half2*)&v;
#pragma unroll
            for (int i = 0; i < 4; ++i) {
                float2 f2 = __half22float2(h2[i]);
                f2.x = LEAKY(f2.x);
                f2.y = LEAKY(f2.y);
                f[t * 8 + i * 2 + 0] = f2.x;
                f[t * 8 + i * 2 + 1] = f2.y;
                s += f2.x + f2.y;
                q += f2.x * f2.x + f2.y * f2.y;
            }
        }
#pragma unroll
        for (int off = 1; off < 32; off <<= 1) {
            s += __shfl_xor_sync(0xffffffffu, s, off);
            q += __shfl_xor_sync(0xffffffffu, q, off);
        }
        float mean = s * (1.0f / 1024.0f);
        float var = q * (1.0f / 1024.0f) - mean * mean;
        float rstd = rsqrtf(var + 1e-5f);
#pragma unroll
        for (int i = 0; i < 32; ++i) acc[i] += (f[i] - mean) * rstd;
    }
#pragma unroll
    for (int t = 0; t < 4; ++t)
#pragma unroll
        for (int j = 0; j < 8; ++j)
            atomicAdd(&sp[lane * 8 + t * 256 + j], acc[t * 8 + j]);
    __syncthreads();

    const float inv = 1.0f / (float)NODES_PER;
    float v0 = sp[tid * 4 + 0] * inv, v1 = sp[tid * 4 + 1] * inv;
    float v2 = sp[tid * 4 + 2] * inv, v3 = sp[tid * 4 + 3] * inv;
    float s = (v0 + v1) + (v2 + v3);
    float q = (v0 * v0 + v1 * v1) + (v2 * v2 + v3 * v3);
#pragma unroll
    for (int off = 1; off < 32; off <<= 1) {
        s += __shfl_xor_sync(0xffffffffu, s, off);
        q += __shfl_xor_sync(0xffffffffu, q, off);
    }
    if (lane == 0) { ss[wid] = s; qq[wid] = q; }
    __syncthreads();
    if (tid == 0) {
        float S = 0.f, Q = 0.f;
#pragma unroll
        for (int w = 0; w < 8; ++w) { S += ss[w]; Q += qq[w]; }
        float mean = S * (1.0f / 1024.0f);
        float var = Q * (1.0f / 1024.0f) - mean * mean;
        s_mean = mean;
        s_rstd = rsqrtf(var + 1e-5f);
    }
    __syncthreads();
    float mean = s_mean, rstd = s_rstd;
    float4 o;
    o.x = (v0 - mean) * rstd; o.y = (v1 - mean) * rstd;
    o.z = (v2 - mean) * rstd; o.w = (v3 - mean) * rstd;
    *(float4*)&pool[b * DBIG + tid * 4] = o;
}

// ---------------- heads ------------------------------------------------------
__global__ void k_out_init(const float* __restrict__ bm, const float* __restrict__ bs,
                           float* __restrict__ out) {
    int i = blockIdx.x * blockDim.x + threadIdx.x;
    if (i < 2 * BATCH_B * DBIG) {
        int n = i & (DBIG - 1);
        out[i] = (i < BATCH_B * DBIG) ? bm[n] : bs[n];
    }
}
__global__ void __launch_bounds__(256) k_head(const float* __restrict__ pool,
                                              const float* __restrict__ Wm,
                                              const float* __restrict__ Ws,
                                              float* __restrict__ out) {
    const float* W = blockIdx.z ? Ws : Wm;
    float* o = out + blockIdx.z * (BATCH_B * DBIG);
    int n0 = blockIdx.x * 64;
    int kc0 = blockIdx.y * 128;
    int tid = threadIdx.x;
    int col = tid & 63;
    int ty = tid >> 6;
    __shared__ float Ap[32 * 136];
    __shared__ float Wsm[32 * 64];
    float acc[32];
#pragma unroll
    for (int r = 0; r < 32; ++r) acc[r] = 0.f;

    for (int kk = 0; kk < 128; kk += 32) {
#pragma unroll
        for (int t = 0; t < 4; ++t) {
            int s = tid + t * 256;
            int row = s >> 3, kq = s & 7;
            float4 v = *(const float4*)&pool[row * DBIG + kc0 + kk + kq * 4];
            Ap[(kq * 4 + 0) * 136 + row] = v.x;
            Ap[(kq * 4 + 1) * 136 + row] = v.y;
            Ap[(kq * 4 + 2) * 136 + row] = v.z;
            Ap[(kq * 4 + 3) * 136 + row] = v.w;
        }
#pragma unroll
        for (int t = 0; t < 2; ++t) {
            int s = tid + t * 256;
            int kr = s >> 4, c4 = s & 15;
            *(float4*)&Wsm[kr * 64 + c4 * 4] =
                *(const float4*)&W[(kc0 + kk + kr) * DBIG + n0 + c4 * 4];
        }
        __syncthreads();
#pragma unroll
        for (int k = 0; k < 32; ++k) {
            float b = Wsm[k * 64 + col];
#pragma unroll
            for (int r4 = 0; r4 < 8; ++r4) {
                float4 a = *(const float4*)&Ap[k * 136 + ty * 32 + r4 * 4];
                acc[r4 * 4 + 0] += a.x * b;
                acc[r4 * 4 + 1] += a.y * b;
                acc[r4 * 4 + 2] += a.z * b;
                acc[r4 * 4 + 3] += a.w * b;
            }
        }
        __syncthreads();
    }
#pragma unroll
    for (int r = 0; r < 32; ++r)
        atomicAdd(&o[(ty * 32 + r) * DBIG + n0 + col], acc[r]);
}

// ---------------- driver ----------------------------------------------------
extern "C" void kernel_launch(void* const* d_in, const int* in_sizes, int n_in,
                              void* d_out, int out_size) {
    const float* x   = (const float*)d_in[0];
    const int*   src = (const int*)d_in[1];
    const int*   dst = (const int*)d_in[2];
    const float* Wl[4] = { (const float*)d_in[3], (const float*)d_in[5],
                           (const float*)d_in[7], (const float*)d_in[9] };
    const float* bl[4] = { (const float*)d_in[4], (const float*)d_in[6],
                           (const float*)d_in[8], (const float*)d_in[10] };
    const float* Wm = (const float*)d_in[11];
    const float* bm = (const float*)d_in[12];
    const float* Ws = (const float*)d_in[13];
    const float* bs = (const float*)d_in[14];
    float* out = (float*)d_out;

    void *p_hs, *p_hbig, *p_pool, *p_wh, *p_ag;
    cudaGetSymbolAddress(&p_hs,   g_hs);
    cudaGetSymbolAddress(&p_hbig, g_hbig);
    cudaGetSymbolAddress(&p_pool, g_pool);
    cudaGetSymbolAddress(&p_wh,   g_whT);
    cudaGetSymbolAddress(&p_ag,   g_agg);
    __half* hs   = (__half*)p_hs;
    __half* hbig = (__half*)p_hbig;
    float* pool  = (float*)p_pool;
    __half* whT  = (__half*)p_wh;
    __half* agg  = (__half*)p_ag;

    cudaFuncSetAttribute(k_gemm_ln, cudaFuncAttributeMaxDynamicSharedMemorySize, GLN_SMEM);

    // graph preprocessing
    k_zero   <<<16, 512>>>();
    k_count  <<<2048, 256>>>(src, dst);
    k_scan   <<<1, 1024>>>();
    k_scatter<<<2048, 256>>>(src, dst);
    k_norms  <<<128, 256>>>();
    k_scale_x<<<8192, 256>>>(x, hs);

    // weight transpose (single fp16, [n][k]); layers 1-3 in one launch
    dim3 tb(32, 8);
    k_prep_w3<<<dim3(8, 8, 3), tb>>>(Wl[0], Wl[1], Wl[2], whT);
    k_prep_w<<<dim3(32, 8), tb>>>(Wl[3], 1024, whT + WT_L4_OFF);

    // layers 1-3: aggregate -> fused GEMM+leaky+LN+ns -> hs
    for (int l = 0; l < 3; ++l) {
        k_aggregate<<<N_NODES / 8, 256>>>(hs, agg);
        k_gemm_ln<<<N_NODES / 128, 512, GLN_SMEM>>>(agg, whT + l * 65536, bl[l], hs);
    }
    // layer 4
    k_aggregate<<<N_NODES / 8, 256>>>(hs, agg);
    k_gemm_mma<<<dim3(8, N_NODES / 128), 256>>>(
        agg, whT + WT_L4_OFF, bl[3], hbig, 1024);

    // fused leaky+LN+pool+poolLN, then heads
    k_lnpool<<<BATCH_B, 256>>>(hbig, pool);
    k_out_init<<<512, 512>>>(bm, bs, out);
    k_head<<<dim3(16, 8, 2), 256>>>(pool, Wm, Ws, out);
}